// round 4
// baseline (speedup 1.0000x reference)
#include <cuda_runtime.h>

// ============================================================================
// MultiHeadAttentionQuantum: per (token, head), simulate 4-qubit circuit.
// Key identity: circuit = fixed per-head 16x16 unitary U_h applied to a REAL
// rank-1 product vector v = ⊗_q (cos(x_q/2), sin(x_q/2)).
//   ev_i = sum_j sign_ij * |(U_h v)_j|^2 ;  out = W ev + b
// Three kernels: (1) build U_h from params, (2) ev for all tokens (f32x2
// packed, 4 tokens/thread), (3) 32x32 output GEMM (f32x2, 2 tokens/thread).
// ============================================================================

#define NQ      4
#define DIM     16
#define NH      8
#define NLAYERS 2
#define EMB     32
#define NTOK    (32 * 4096)

typedef unsigned long long ull;

// ---- packed f32x2 helpers (Blackwell sm_103a) ------------------------------
__device__ __forceinline__ ull pk(float lo, float hi) {
    ull r; asm("mov.b64 %0, {%1, %2};" : "=l"(r) : "f"(lo), "f"(hi)); return r;
}
__device__ __forceinline__ void upk(ull v, float& lo, float& hi) {
    asm("mov.b64 {%0, %1}, %2;" : "=f"(lo), "=f"(hi) : "l"(v));
}
__device__ __forceinline__ ull f2mul(ull a, ull b) {
    ull d; asm("mul.rn.f32x2 %0, %1, %2;" : "=l"(d) : "l"(a), "l"(b)); return d;
}
__device__ __forceinline__ ull f2fma(ull a, ull b, ull c) {
    ull d; asm("fma.rn.f32x2 %0, %1, %2, %3;" : "=l"(d) : "l"(a), "l"(b), "l"(c)); return d;
}

// ---- global scratch (static device arrays; no allocation) ------------------
// g_U[h*256 + j*16 + k] = { dup(Re U[j][k]), dup(Im U[j][k]) }
__device__ ulonglong2 g_U[NH * 256];
__device__ float      g_ev[(size_t)NTOK * EMB];   // 16 MB scratch

// ============================================================================
// Kernel 1: build per-head unitary U_h (16x16 complex) by gate composition.
// One warp per head; lanes 0..15 each own one COLUMN of U (a 16-dim state).
// ============================================================================
__global__ void precompute_U_kernel(const float* __restrict__ params) {
    int lane = threadIdx.x & 31;
    int h    = threadIdx.x >> 5;
    if (lane >= DIM || h >= NH) return;

    float cr[DIM], ci[DIM];
#pragma unroll
    for (int j = 0; j < DIM; ++j) { cr[j] = (j == lane) ? 1.0f : 0.0f; ci[j] = 0.0f; }

#pragma unroll
    for (int l = 0; l < NLAYERS; ++l) {
#pragma unroll
        for (int q = 0; q < NQ; ++q) {
            const float* p = params + (((h * NLAYERS) + l) * NQ + q) * 3;
            const int mask = 1 << (3 - q);   // qubit q bit stride = 2^(3-q)
            // ---- RX(t): [[c, -is],[-is, c]], c=cos(t/2), s=sin(t/2)
            {
                float t = p[0], c = cosf(0.5f * t), s = sinf(0.5f * t);
#pragma unroll
                for (int j = 0; j < DIM; ++j) if (!(j & mask)) {
                    int j1 = j | mask;
                    float a0r = cr[j],  a0i = ci[j];
                    float a1r = cr[j1], a1i = ci[j1];
                    cr[j]  = c * a0r + s * a1i;   ci[j]  = c * a0i - s * a1r;
                    cr[j1] = c * a1r + s * a0i;   ci[j1] = c * a1i - s * a0r;
                }
            }
            // ---- RY(t): [[c, -s],[s, c]] (real)
            {
                float t = p[1], c = cosf(0.5f * t), s = sinf(0.5f * t);
#pragma unroll
                for (int j = 0; j < DIM; ++j) if (!(j & mask)) {
                    int j1 = j | mask;
                    float a0r = cr[j],  a0i = ci[j];
                    float a1r = cr[j1], a1i = ci[j1];
                    cr[j]  = c * a0r - s * a1r;   ci[j]  = c * a0i - s * a1i;
                    cr[j1] = s * a0r + c * a1r;   ci[j1] = s * a0i + c * a1i;
                }
            }
            // ---- RZ(t): diag(e^{-it/2}, e^{+it/2})
            {
                float t = p[2], c = cosf(0.5f * t), s = sinf(0.5f * t);
#pragma unroll
                for (int j = 0; j < DIM; ++j) if (!(j & mask)) {
                    int j1 = j | mask;
                    float a0r = cr[j],  a0i = ci[j];
                    float a1r = cr[j1], a1i = ci[j1];
                    cr[j]  = c * a0r + s * a0i;   ci[j]  = c * a0i - s * a0r;
                    cr[j1] = c * a1r - s * a1i;   ci[j1] = c * a1i + s * a1r;
                }
            }
        }
        // ---- CNOT ring: (0,1),(1,2),(2,3),(3,0)  [control, target]
        auto cnot = [&](int cq, int tq) {
            int cm = 1 << (3 - cq), tm = 1 << (3 - tq);
#pragma unroll
            for (int j = 0; j < DIM; ++j) if ((j & cm) && !(j & tm)) {
                int j1 = j | tm;
                float tr = cr[j]; cr[j] = cr[j1]; cr[j1] = tr;
                float ti = ci[j]; ci[j] = ci[j1]; ci[j1] = ti;
            }
        };
        cnot(0, 1); cnot(1, 2); cnot(2, 3); cnot(3, 0);
    }

#pragma unroll
    for (int j = 0; j < DIM; ++j) {
        ulonglong2 u;
        u.x = pk(cr[j], cr[j]);
        u.y = pk(ci[j], ci[j]);
        g_U[h * 256 + j * 16 + lane] = u;   // lane = column index k
    }
}

// ============================================================================
// Kernel 2: ev for all tokens. 4 tokens per thread as two f32x2 pairs.
// ============================================================================
__global__ __launch_bounds__(128) void ev_kernel(const float* __restrict__ x) {
    __shared__ ulonglong2 sU[NH * 256];   // 32 KB
    for (int i = threadIdx.x; i < NH * 256; i += blockDim.x) sU[i] = g_U[i];
    __syncthreads();

    const int gid = blockIdx.x * blockDim.x + threadIdx.x;
    const int t0  = gid * 4;
    const ull PONE = pk(1.0f, 1.0f);
    const ull MONE = pk(-1.0f, -1.0f);

#pragma unroll 1
    for (int h = 0; h < NH; ++h) {
        ull v[2][16];
#pragma unroll
        for (int p = 0; p < 2; ++p) {
            const int ta = t0 + 2 * p;
            float4 aa = *reinterpret_cast<const float4*>(x + (size_t)ta * EMB + h * 4);
            float4 ab = *reinterpret_cast<const float4*>(x + (size_t)(ta + 1) * EMB + h * 4);
            ull c0 = pk(__cosf(0.5f * aa.x), __cosf(0.5f * ab.x));
            ull s0 = pk(__sinf(0.5f * aa.x), __sinf(0.5f * ab.x));
            ull c1 = pk(__cosf(0.5f * aa.y), __cosf(0.5f * ab.y));
            ull s1 = pk(__sinf(0.5f * aa.y), __sinf(0.5f * ab.y));
            ull c2 = pk(__cosf(0.5f * aa.z), __cosf(0.5f * ab.z));
            ull s2 = pk(__sinf(0.5f * aa.z), __sinf(0.5f * ab.z));
            ull c3 = pk(__cosf(0.5f * aa.w), __cosf(0.5f * ab.w));
            ull s3 = pk(__sinf(0.5f * aa.w), __sinf(0.5f * ab.w));
            ull v01[4] = { f2mul(c0, c1), f2mul(c0, s1), f2mul(s0, c1), f2mul(s0, s1) };
            ull v23[4] = { f2mul(c2, c3), f2mul(c2, s3), f2mul(s2, c3), f2mul(s2, s3) };
#pragma unroll
            for (int a = 0; a < 4; ++a)
#pragma unroll
                for (int b = 0; b < 4; ++b)
                    v[p][a * 4 + b] = f2mul(v01[a], v23[b]);
        }

        ull ev[2][4];
#pragma unroll
        for (int p = 0; p < 2; ++p)
#pragma unroll
            for (int i = 0; i < 4; ++i) ev[p][i] = 0ull;  // 0.0f|0.0f

        const ulonglong2* Uh = sU + h * 256;
#pragma unroll
        for (int j = 0; j < 16; ++j) {
            ulonglong2 u = Uh[j * 16];
            ull ar0 = f2mul(u.x, v[0][0]), ai0 = f2mul(u.y, v[0][0]);
            ull ar1 = f2mul(u.x, v[1][0]), ai1 = f2mul(u.y, v[1][0]);
#pragma unroll
            for (int k = 1; k < 16; ++k) {
                u = Uh[j * 16 + k];
                ar0 = f2fma(u.x, v[0][k], ar0);  ai0 = f2fma(u.y, v[0][k], ai0);
                ar1 = f2fma(u.x, v[1][k], ar1);  ai1 = f2fma(u.y, v[1][k], ai1);
            }
            ull p0 = f2fma(ar0, ar0, f2mul(ai0, ai0));
            ull p1 = f2fma(ar1, ar1, f2mul(ai1, ai1));
#pragma unroll
            for (int i = 0; i < 4; ++i) {
                const ull sg = ((j >> (3 - i)) & 1) ? MONE : PONE;  // compile-time
                ev[0][i] = f2fma(p0, sg, ev[0][i]);
                ev[1][i] = f2fma(p1, sg, ev[1][i]);
            }
        }

#pragma unroll
        for (int p = 0; p < 2; ++p) {
            const int ta = t0 + 2 * p;
            float l0, h0, l1, h1, l2, h2, l3, h3;
            upk(ev[p][0], l0, h0); upk(ev[p][1], l1, h1);
            upk(ev[p][2], l2, h2); upk(ev[p][3], l3, h3);
            *reinterpret_cast<float4*>(g_ev + (size_t)ta * EMB + h * 4)       = make_float4(l0, l1, l2, l3);
            *reinterpret_cast<float4*>(g_ev + (size_t)(ta + 1) * EMB + h * 4) = make_float4(h0, h1, h2, h3);
        }
    }
}

// ============================================================================
// Kernel 3: out[t] = W * ev[t] + b.  2 tokens per thread (one f32x2 pair).
// ============================================================================
__global__ __launch_bounds__(128) void out_kernel(const float* __restrict__ W,
                                                  const float* __restrict__ bvec,
                                                  float* __restrict__ out) {
    __shared__ ulonglong2 sW[EMB * 16];   // [e][fpair] = {dup(W[e][2f]), dup(W[e][2f+1])}
    __shared__ float sb[EMB];
    for (int i = threadIdx.x; i < EMB * 16; i += blockDim.x) {
        int e = i >> 4, fp = i & 15;
        float w0 = W[e * 32 + fp * 2], w1 = W[e * 32 + fp * 2 + 1];
        ulonglong2 u; u.x = pk(w0, w0); u.y = pk(w1, w1);
        sW[i] = u;
    }
    if (threadIdx.x < EMB) sb[threadIdx.x] = bvec[threadIdx.x];
    __syncthreads();

    const int gid = blockIdx.x * blockDim.x + threadIdx.x;
    const int t0 = gid * 2, t1 = t0 + 1;

    ull ev2[32];
#pragma unroll
    for (int m = 0; m < 8; ++m) {
        float4 e0 = *reinterpret_cast<const float4*>(g_ev + (size_t)t0 * EMB + m * 4);
        float4 e1 = *reinterpret_cast<const float4*>(g_ev + (size_t)t1 * EMB + m * 4);
        ev2[m * 4 + 0] = pk(e0.x, e1.x);
        ev2[m * 4 + 1] = pk(e0.y, e1.y);
        ev2[m * 4 + 2] = pk(e0.z, e1.z);
        ev2[m * 4 + 3] = pk(e0.w, e1.w);
    }

#pragma unroll 1
    for (int eg = 0; eg < 8; ++eg) {
        float o0[4], o1[4];
#pragma unroll
        for (int r = 0; r < 4; ++r) {
            const int e = eg * 4 + r;
            float be = sb[e];
            ull acc = pk(be, be);
#pragma unroll
            for (int fp = 0; fp < 16; ++fp) {
                ulonglong2 w = sW[e * 16 + fp];
                acc = f2fma(w.x, ev2[fp * 2],     acc);
                acc = f2fma(w.y, ev2[fp * 2 + 1], acc);
            }
            upk(acc, o0[r], o1[r]);
        }
        *reinterpret_cast<float4*>(out + (size_t)t0 * EMB + eg * 4) = make_float4(o0[0], o0[1], o0[2], o0[3]);
        *reinterpret_cast<float4*>(out + (size_t)t1 * EMB + eg * 4) = make_float4(o1[0], o1[1], o1[2], o1[3]);
    }
}

// ============================================================================
extern "C" void kernel_launch(void* const* d_in, const int* in_sizes, int n_in,
                              void* d_out, int out_size) {
    // Identify inputs robustly by element count (all distinct):
    // x: 32*4096*32 = 4194304, params: 8*2*4*3 = 192, W_out: 32*32 = 1024, b_out: 32
    const float* x = 0; const float* params = 0; const float* W = 0; const float* b = 0;
    for (int i = 0; i < n_in; ++i) {
        switch (in_sizes[i]) {
            case 4194304: x      = (const float*)d_in[i]; break;
            case 192:     params = (const float*)d_in[i]; break;
            case 1024:    W      = (const float*)d_in[i]; break;
            case 32:      b      = (const float*)d_in[i]; break;
            default: break;
        }
    }
    float* out = (float*)d_out;

    precompute_U_kernel<<<1, 256>>>(params);
    ev_kernel<<<256, 128>>>(x);          // 32768 threads * 4 tokens = 131072
    out_kernel<<<512, 128>>>(W, b, out); // 65536 threads * 2 tokens = 131072
}